// round 16
// baseline (speedup 1.0000x reference)
#include <cuda_runtime.h>
#include <math.h>

#define H 1024
#define VOCAB 50257
#define GATE_HALF 512           // blocks per gate half (8 rows each)
#define LOGIT_NPB 6283          // ceil(50257 / 8)
#define FIN_BLOCKS 197          // ceil(50257 / 256)

// Scratch (__device__ globals — allocation-free rule)
__device__ float g_partA[8192];   // layer1: [0,4096)=Wih·x, [4096,8192)=Whh·h
__device__ float g_partB[8192];   // layer2
__device__ float g_h1[H], g_h1r[H], g_c1[H], g_h2[H];
__device__ float2 g_pairs[LOGIT_NPB];

// ---------------------------------------------------------------------------
__device__ __forceinline__ float sigmoidf_fast(float x) {
    return 1.f / (1.f + __expf(-x));
}

__device__ __forceinline__ void merge_pair(float& m, float& s, float m2, float s2) {
    if (m2 > m) { float t = s; s = s2 + t * __expf(m - m2); m = m2; }
    else if (m2 != -INFINITY) { s += s2 * __expf(m2 - m); }
}

// 256-bit loads (LDG.E.256)
struct f8 { float4 a, b; };

__device__ __forceinline__ f8 ld8(const float* p) {
    f8 v;
    asm volatile(
        "{\n\t.reg .b64 q0,q1,q2,q3;\n\t"
        "ld.global.nc.v4.b64 {q0,q1,q2,q3}, [%8];\n\t"
        "mov.b64 {%0,%1}, q0;\n\tmov.b64 {%2,%3}, q1;\n\t"
        "mov.b64 {%4,%5}, q2;\n\tmov.b64 {%6,%7}, q3;\n\t}"
        : "=f"(v.a.x), "=f"(v.a.y), "=f"(v.a.z), "=f"(v.a.w),
          "=f"(v.b.x), "=f"(v.b.y), "=f"(v.b.z), "=f"(v.b.w)
        : "l"(p));
    return v;
}

__device__ __forceinline__ void row_load(const float* W, int lane, f8 w[4]) {
#pragma unroll
    for (int k = 0; k < 4; k++) w[k] = ld8(W + (k * 32 + lane) * 8);
}

__device__ __forceinline__ float dot8(const f8& w, const float4& x0, const float4& x1) {
    return w.a.x * x0.x + w.a.y * x0.y + w.a.z * x0.z + w.a.w * x0.w
         + w.b.x * x1.x + w.b.y * x1.y + w.b.z * x1.z + w.b.w * x1.w;
}

__device__ __forceinline__ float row_dot(const f8 w[4], const float4* v4, int lane) {
    float acc = 0.f;
#pragma unroll
    for (int k = 0; k < 4; k++) {
        int c = (k * 32 + lane) * 2;
        acc += dot8(w[k], v4[c], v4[c + 1]);
    }
    return acc;
}

__device__ __forceinline__ float warp_sum(float acc) {
#pragma unroll
    for (int o = 16; o > 0; o >>= 1) acc += __shfl_down_sync(0xffffffffu, acc, o);
    return acc;
}

// ---------------------------------------------------------------------------
// Gates GEMV: 1024 blocks x 256 thr. Blocks [0,512): Wih rows vs relu(x);
// blocks [512,1024): Whh rows vs h. All-zero source halves write 0, no loads.
// x source: emb[id[0]] when idptr != null (layer 1), else xsrc.
// ---------------------------------------------------------------------------
__global__ void __launch_bounds__(256) gates_kernel(
        const float* __restrict__ Wih, const float* __restrict__ Whh,
        const float* __restrict__ xsrc, const int* __restrict__ idptr,
        const float* __restrict__ hsrc, float* __restrict__ part) {
    __shared__ float sv[H];
    __shared__ int s_nz;
    int t = threadIdx.x;
    bool isA = blockIdx.x < GATE_HALF;

    if (t == 0) s_nz = 0;
    __syncthreads();
    if (isA) {
        const float* x = idptr ? (xsrc + (long)idptr[0] * H) : xsrc;
        for (int i = t; i < H; i += 256) {
            float v = fmaxf(x[i], 0.f);
            sv[i] = v;
            if (v != 0.f) s_nz = 1;
        }
    } else {
        for (int i = t; i < H; i += 256) {
            float v = hsrc[i];
            sv[i] = v;
            if (v != 0.f) s_nz = 1;
        }
    }
    __syncthreads();

    int warp = t >> 5, lane = t & 31;
    int row = (blockIdx.x & (GATE_HALF - 1)) * 8 + warp;   // [0, 4096)
    int pidx = (isA ? 0 : 4096) + row;

    if (!s_nz) {                 // zero input vector: partials are exactly 0
        if (lane == 0) part[pidx] = 0.f;
        return;
    }

    const float* W = (isA ? Wih : Whh) + (long)row * H;
    f8 w[4];
    row_load(W, lane, w);
    float acc = row_dot(w, (const float4*)sv, lane);
    acc = warp_sum(acc);
    if (lane == 0) part[pidx] = acc;
}

// ---------------------------------------------------------------------------
// LSTM elementwise: 4 blocks x 256 (one thread per h-element).
// torch gate order i, f, g, o.
// ---------------------------------------------------------------------------
__global__ void __launch_bounds__(256) act_kernel(
        const float* __restrict__ part,
        const float* __restrict__ bih, const float* __restrict__ bhh,
        const float* __restrict__ cin,
        float* __restrict__ hraw, float* __restrict__ hrelu,
        float* __restrict__ cout,
        float* __restrict__ tail, int write_tail) {
    int j = blockIdx.x * 256 + threadIdx.x;            // [0, 1024)
    float gi = part[j]         + part[4096 + j]         + bih[j]         + bhh[j];
    float gf = part[j + H]     + part[4096 + j + H]     + bih[j + H]     + bhh[j + H];
    float gg = part[j + 2 * H] + part[4096 + j + 2 * H] + bih[j + 2 * H] + bhh[j + 2 * H];
    float go = part[j + 3 * H] + part[4096 + j + 3 * H] + bih[j + 3 * H] + bhh[j + 3 * H];
    float cn = sigmoidf_fast(gf) * cin[j] + sigmoidf_fast(gi) * tanhf(gg);
    float hn = sigmoidf_fast(go) * tanhf(cn);
    hraw[j] = hn;
    if (hrelu) hrelu[j] = fmaxf(hn, 0.f);
    cout[j] = cn;
    if (write_tail) {
        tail[j]     = hn;
        tail[H + j] = cn;
    }
}

// ---------------------------------------------------------------------------
// Logits GEMV: 6283 blocks x 256 thr, warp-per-row (8 rows/block), block
// churn keeps ~40 warps/SM streaming. Emits logits + per-block online pair.
// ---------------------------------------------------------------------------
__global__ void __launch_bounds__(256, 5) logits_kernel(
        const float* __restrict__ Wout, const float* __restrict__ bout,
        float* __restrict__ out) {
    __shared__ float sh[H];
    __shared__ float2 wpairs[8];
    int t = threadIdx.x, lane = t & 31, warp = t >> 5;

    for (int i = t; i < H; i += 256) sh[i] = g_h2[i];
    __syncthreads();

    int row = blockIdx.x * 8 + warp;
    int rc = row < VOCAB ? row : 0;        // clamp: loads always valid
    f8 w[4];
    row_load(Wout + (long)rc * H, lane, w);
    float acc = row_dot(w, (const float4*)sh, lane);
    acc = warp_sum(acc);

    if (lane == 0) {
        float m = -INFINITY, s = 0.f;
        if (row < VOCAB) {
            float v = acc + bout[row];
            out[row] = v;
            m = v; s = 1.0f;
        }
        wpairs[warp] = make_float2(m, s);
    }
    __syncthreads();
    if (t == 0) {
        float mm = wpairs[0].x, ss = wpairs[0].y;
#pragma unroll
        for (int wq = 1; wq < 8; wq++) merge_pair(mm, ss, wpairs[wq].x, wpairs[wq].y);
        g_pairs[blockIdx.x] = make_float2(mm, ss);
    }
}

// ---------------------------------------------------------------------------
// finish: each block redundantly reduces all pairs (~50KB, L2-resident) to
// lse (identical order => identical bits), then subtracts from its slice.
// ---------------------------------------------------------------------------
__global__ void __launch_bounds__(256) finish_kernel(float* __restrict__ out) {
    __shared__ float2 red[8];
    __shared__ float s_lse;
    int t = threadIdx.x, lane = t & 31, warp = t >> 5;

    float m = -INFINITY, s = 0.f;
    for (int i = t; i < LOGIT_NPB; i += 256) {
        float2 p = g_pairs[i];
        merge_pair(m, s, p.x, p.y);
    }
#pragma unroll
    for (int o = 16; o > 0; o >>= 1) {
        float m2 = __shfl_down_sync(0xffffffffu, m, o);
        float s2 = __shfl_down_sync(0xffffffffu, s, o);
        merge_pair(m, s, m2, s2);
    }
    if (lane == 0) red[warp] = make_float2(m, s);
    __syncthreads();
    if (t == 0) {
        m = red[0].x; s = red[0].y;
#pragma unroll
        for (int wq = 1; wq < 8; wq++) merge_pair(m, s, red[wq].x, red[wq].y);
        s_lse = m + logf(s);
    }
    __syncthreads();

    int i = blockIdx.x * 256 + t;
    if (i < VOCAB) out[i] -= s_lse;
}

// ---------------------------------------------------------------------------
extern "C" void kernel_launch(void* const* d_in, const int* in_sizes, int n_in,
                              void* d_out, int out_size) {
    const int*   id   = (const int*)d_in[0];
    const float* h0   = (const float*)d_in[1];
    const float* c0   = (const float*)d_in[2];
    const float* emb  = (const float*)d_in[3];
    const float* Wih  = (const float*)d_in[4];
    const float* Whh  = (const float*)d_in[5];
    const float* bih  = (const float*)d_in[6];
    const float* bhh  = (const float*)d_in[7];
    const float* Wout = (const float*)d_in[8];
    const float* bout = (const float*)d_in[9];
    float* out = (float*)d_out;

    float *pA, *pB, *gh1, *gh1r, *gc1, *gh2;
    cudaGetSymbolAddress((void**)&pA,   g_partA);
    cudaGetSymbolAddress((void**)&pB,   g_partB);
    cudaGetSymbolAddress((void**)&gh1,  g_h1);
    cudaGetSymbolAddress((void**)&gh1r, g_h1r);
    cudaGetSymbolAddress((void**)&gc1,  g_c1);
    cudaGetSymbolAddress((void**)&gh2,  g_h2);

    int write_tail = (out_size >= VOCAB + 2 * H) ? 1 : 0;

    // layer 1: x = relu(emb[id]) (fused), h = h0 (zero half auto-skipped)
    gates_kernel<<<2 * GATE_HALF, 256>>>(Wih, Whh, emb, id, h0, pA);
    act_kernel<<<4, 256>>>(pA, bih, bhh, c0, gh1, gh1r, gc1, out + VOCAB, 0);

    // layer 2: x = relu(h1), h = h1 (same weights per reference)
    gates_kernel<<<2 * GATE_HALF, 256>>>(Wih, Whh, gh1r, nullptr, gh1, pB);
    act_kernel<<<4, 256>>>(pB, bih, bhh, gc1, gh2, nullptr, gc1, out + VOCAB, write_tail);

    // vocab projection (+ online softmax pairs), then lse + subtract
    logits_kernel<<<LOGIT_NPB, 256>>>(Wout, bout, out);
    finish_kernel<<<FIN_BLOCKS, 256>>>(out);
}